// round 11
// baseline (speedup 1.0000x reference)
#include <cuda_runtime.h>

#define NBLK 2048   // 256 batches * 8 block-chunks; block = 2 warps * 8 rows each
#define NTHR 64     // 2 warps

__device__ float g_part[NBLK][4];
__device__ unsigned int g_ctr;

__global__ __launch_bounds__(NTHR, 8) void physics_kernel(
    const float* __restrict__ inp,   // (256,1,128,128)
    const float* __restrict__ outp,  // (256,3,128,128)
    const float* __restrict__ tgt,   // (256,3,128,128)
    float* __restrict__ out)
{
    const int blk  = blockIdx.x;
    const int b    = blk >> 3;
    const int q    = blk & 7;
    const int tx   = threadIdx.x;
    const int lane = tx & 31;
    const int w    = tx >> 5;

    constexpr float INV_SX  = 127.0f / 1.2f;
    constexpr float INV_2SX = 127.0f / 2.4f;
    constexpr float INV_SY  = 127.0f / 0.8f;
    constexpr float INV_2SY = 127.0f / 1.6f;
    constexpr float C2X = INV_2SX * INV_2SX;
    constexpr float C2Y = INV_2SY * INV_2SY;

    const float* Ob = outp + b * 49152;
    const float* Tb = tgt  + b * 49152;
    const float* Ib = inp  + b * 16384;

    // split accumulators to break FMA dependency chains
    float sb0 = 0.f, sb1 = 0.f, sb2 = 0.f, sb3 = 0.f;
    float sc0 = 0.f, sc1 = 0.f;
    float sn0 = 0.f, sn1 = 0.f;
    float s_bc = 0.f;

    // ---------------- fused PDE + base/boundary loop ----------------
    const int chunk = q * 2 + w;                 // 0..15
    const int y0  = chunk * 8;
    const int jlo = max(y0 - 1, 0);
    const int jhi = min(y0 + 7, 126);
    const int npde = jhi - jlo;                  // 7 or 8

    const float4* O4 = (const float4*)Ob;
    const float4* T4 = (const float4*)Tb;
    const float4* U4 = (const float4*)(Ob + 16384);
    const float4* V4 = (const float4*)(Ob + 32768);
    const float4* P4 = (const float4*)(Ob);
    const float4* A4 = (const float4*)(Ib);

#define ROWI(j) (((j) + 1) * 32 + lane)
#define LD4(dst, arrptr, j) { float4 _t = (arrptr)[ROWI(j)]; \
        dst[0]=_t.x; dst[1]=_t.y; dst[2]=_t.z; dst[3]=_t.w; }
#define LD4S(dst, arrptr, j) { float4 _t = __ldcs(&(arrptr)[ROWI(j)]); \
        dst[0]=_t.x; dst[1]=_t.y; dst[2]=_t.z; dst[3]=_t.w; }

    float um2[4], um1[4], uc[4], up1[4], up2[4];
    float vm2[4], vm1[4], vc[4], vp1[4], vp2[4];
    float pm1[4], pc[4], pp1[4];
#pragma unroll
    for (int t = 0; t < 4; ++t) {
        um2[t] = um1[t] = 0.f; vm2[t] = vm1[t] = 0.f; pm1[t] = 0.f;
    }

    if (jlo >= 2) { LD4(um2, U4, jlo - 2); LD4(vm2, V4, jlo - 2); }
    if (jlo >= 1) { LD4(um1, U4, jlo - 1); LD4(vm1, V4, jlo - 1); LD4(pm1, P4, jlo - 1); }
    LD4(uc,  U4, jlo);      LD4(vc,  V4, jlo);      LD4(pc,  P4, jlo);
    LD4(up1, U4, jlo + 1);  LD4(vp1, V4, jlo + 1);  LD4(pp1, P4, jlo + 1);
    LD4(up2, U4, jlo + 2);  LD4(vp2, V4, jlo + 2);

    float wt[4] = {1.f, 1.f, 1.f, 1.f};
    if (lane == 0)  wt[0] = 0.f;
    if (lane == 31) wt[3] = 0.f;

#pragma unroll
    for (int it = 0; it < 8; ++it) {
        const int j = jlo + it;
        const bool pde = (it < 7) || (it < npde);   // it<7 always pde; it==7 only if npde==8

        // ---- issue ALL loads up front ----
        float nu[4] = {0,0,0,0}, nv[4] = {0,0,0,0}, np[4] = {0,0,0,0}, al[4] = {0,0,0,0};
        if (pde) {
            if (j + 3 <= 125) { LD4(nu, U4, j + 3); LD4(nv, V4, j + 3); }
            if (j + 2 <= 125) { LD4(np, P4, j + 2); }
            LD4S(al, A4, j);
        }
        const int yb   = y0 + it;                 // base row (8 per warp, all valid)
        const int bidx = yb * 32 + lane;
        float4 o0 = O4[bidx], o1 = O4[4096 + bidx], o2 = O4[8192 + bidx];
        float4 t0 = __ldcs(&T4[bidx]);
        float4 t1 = __ldcs(&T4[4096 + bidx]);
        float4 t2 = __ldcs(&T4[8192 + bidx]);

        // ---- base + boundary compute ----
        {
            float d;
            d = o0.x - t0.x; sb0 += d * d;  d = o0.y - t0.y; sb1 += d * d;
            d = o0.z - t0.z; sb2 += d * d;  d = o0.w - t0.w; sb3 += d * d;
            d = o1.x - t1.x; sb0 += d * d;  d = o1.y - t1.y; sb1 += d * d;
            d = o1.z - t1.z; sb2 += d * d;  d = o1.w - t1.w; sb3 += d * d;
            d = o2.x - t2.x; sb0 += d * d;  d = o2.y - t2.y; sb1 += d * d;
            d = o2.z - t2.z; sb2 += d * d;  d = o2.w - t2.w; sb3 += d * d;

            bool midrow = (yb >= 55) && (yb < 73);
            if (yb == 0 || yb == 127)
                s_bc += o1.x * o1.x + o1.y * o1.y + o1.z * o1.z + o1.w * o1.w
                      + o2.x * o2.x + o2.y * o2.y + o2.z * o2.z + o2.w * o2.w;
            if (lane == 0) {
                if (midrow) { float e = o1.x - 0.01f; s_bc += e * e; }
                else        s_bc += o1.x * o1.x + o2.x * o2.x;
            }
            if (lane == 31) {
                if (midrow) s_bc += o0.w * o0.w;
                else        s_bc += o1.w * o1.w + o2.w * o2.w;
            }
        }

        // ---- PDE compute ----
        if (pde) {
            // x-halo shuffles
            float upz = __shfl_up_sync(0xffffffffu, uc[2], 1);
            float upw = __shfl_up_sync(0xffffffffu, uc[3], 1);
            float unx = __shfl_down_sync(0xffffffffu, uc[0], 1);
            float uny = __shfl_down_sync(0xffffffffu, uc[1], 1);
            float vpz = __shfl_up_sync(0xffffffffu, vc[2], 1);
            float vpw = __shfl_up_sync(0xffffffffu, vc[3], 1);
            float vnx = __shfl_down_sync(0xffffffffu, vc[0], 1);
            float vny = __shfl_down_sync(0xffffffffu, vc[1], 1);
            float ppw = __shfl_up_sync(0xffffffffu, pc[3], 1);
            float pnx = __shfl_down_sync(0xffffffffu, pc[0], 1);

            float uw[8] = {upz, upw, uc[0], uc[1], uc[2], uc[3], unx, uny};
            float vw[8] = {vpz, vpw, vc[0], vc[1], vc[2], vc[3], vnx, vny};
            float pw[8] = {0.f, ppw, pc[0], pc[1], pc[2], pc[3], pnx, 0.f};

            float du_dx[4], du_dxx[4], dv_dx[4], dv_dxx[4], dp_dx[4];
#pragma unroll
            for (int t = 0; t < 4; ++t) {
                du_dx[t]  = (uw[t + 3] - uw[t + 1]) * INV_2SX;
                du_dxx[t] = (uw[t + 4] - 2.f * uw[t + 2] + uw[t]) * C2X;
                dv_dx[t]  = (vw[t + 3] - vw[t + 1]) * INV_2SX;
                dv_dxx[t] = (vw[t + 4] - 2.f * vw[t + 2] + vw[t]) * C2X;
                dp_dx[t]  = (pw[t + 3] - pw[t + 1]) * INV_2SX;
            }
            if (lane == 0) {
                du_dx[1]  = (uw[4] - uw[3]) * INV_SX;
                du_dxx[1] = ((uw[5] - uw[3]) * INV_2SX - (uw[4] - uw[3]) * INV_SX) * INV_SX;
                du_dxx[2] = ((uw[6] - uw[4]) * INV_2SX - (uw[4] - uw[3]) * INV_SX) * INV_2SX;
                dv_dx[1]  = (vw[4] - vw[3]) * INV_SX;
                dv_dxx[1] = ((vw[5] - vw[3]) * INV_2SX - (vw[4] - vw[3]) * INV_SX) * INV_SX;
                dv_dxx[2] = ((vw[6] - vw[4]) * INV_2SX - (vw[4] - vw[3]) * INV_SX) * INV_2SX;
                dp_dx[1]  = (pw[4] - pw[3]) * INV_SX;
            }
            if (lane == 31) {
                du_dxx[1] = ((uw[4] - uw[3]) * INV_SX - (uw[3] - uw[1]) * INV_2SX) * INV_2SX;
                du_dx[2]  = (uw[4] - uw[3]) * INV_SX;
                du_dxx[2] = ((uw[4] - uw[3]) * INV_SX - (uw[4] - uw[2]) * INV_2SX) * INV_SX;
                dv_dxx[1] = ((vw[4] - vw[3]) * INV_SX - (vw[3] - vw[1]) * INV_2SX) * INV_2SX;
                dv_dx[2]  = (vw[4] - vw[3]) * INV_SX;
                dv_dxx[2] = ((vw[4] - vw[3]) * INV_SX - (vw[4] - vw[2]) * INV_2SX) * INV_SX;
                dp_dx[2]  = (pw[4] - pw[3]) * INV_SX;
            }

            // y-direction (warp-uniform class)
            float du_dy[4], du_dyy[4], dv_dy[4], dv_dyy[4], dp_dy[4];
#pragma unroll
            for (int t = 0; t < 4; ++t) {
                du_dy[t]  = (up1[t] - um1[t]) * INV_2SY;
                du_dyy[t] = (up2[t] - 2.f * uc[t] + um2[t]) * C2Y;
                dv_dy[t]  = (vp1[t] - vm1[t]) * INV_2SY;
                dv_dyy[t] = (vp2[t] - 2.f * vc[t] + vm2[t]) * C2Y;
                dp_dy[t]  = (pp1[t] - pm1[t]) * INV_2SY;
            }
            if (j < 2 || j > 123) {
                if (j == 0) {
#pragma unroll
                    for (int t = 0; t < 4; ++t) {
                        du_dy[t]  = (up1[t] - uc[t]) * INV_SY;
                        du_dyy[t] = ((up2[t] - uc[t]) * INV_2SY - (up1[t] - uc[t]) * INV_SY) * INV_SY;
                        dv_dy[t]  = (vp1[t] - vc[t]) * INV_SY;
                        dv_dyy[t] = ((vp2[t] - vc[t]) * INV_2SY - (vp1[t] - vc[t]) * INV_SY) * INV_SY;
                        dp_dy[t]  = (pp1[t] - pc[t]) * INV_SY;
                    }
                } else if (j == 1) {
#pragma unroll
                    for (int t = 0; t < 4; ++t) {
                        du_dyy[t] = ((up2[t] - uc[t]) * INV_2SY - (uc[t] - um1[t]) * INV_SY) * INV_2SY;
                        dv_dyy[t] = ((vp2[t] - vc[t]) * INV_2SY - (vc[t] - vm1[t]) * INV_SY) * INV_2SY;
                    }
                } else if (j == 124) {
#pragma unroll
                    for (int t = 0; t < 4; ++t) {
                        du_dyy[t] = ((up1[t] - uc[t]) * INV_SY - (uc[t] - um2[t]) * INV_2SY) * INV_2SY;
                        dv_dyy[t] = ((vp1[t] - vc[t]) * INV_SY - (vc[t] - vm2[t]) * INV_2SY) * INV_2SY;
                    }
                } else { // j == 125
#pragma unroll
                    for (int t = 0; t < 4; ++t) {
                        du_dy[t]  = (uc[t] - um1[t]) * INV_SY;
                        du_dyy[t] = ((uc[t] - um1[t]) * INV_SY - (uc[t] - um2[t]) * INV_2SY) * INV_SY;
                        dv_dy[t]  = (vc[t] - vm1[t]) * INV_SY;
                        dv_dyy[t] = ((vc[t] - vm1[t]) * INV_SY - (vc[t] - vm2[t]) * INV_2SY) * INV_SY;
                        dp_dy[t]  = (pc[t] - pm1[t]) * INV_SY;
                    }
                }
            }

            // residuals: 2 independent accumulator chains each
#pragma unroll
            for (int t = 0; t < 4; ++t) {
                float div = du_dx[t] + dv_dy[t];
                float cadd = wt[t] * div * div;
                if (t & 1) sc1 += cadd; else sc0 += cadd;
                float xr = uc[t] * du_dx[t] + vc[t] * du_dy[t] + dp_dx[t]
                         - (du_dxx[t] + du_dyy[t]) + al[t] * uc[t];
                float yr = uc[t] * dv_dx[t] + vc[t] * dv_dy[t] + dp_dy[t]
                         - (dv_dxx[t] + dv_dyy[t]) + al[t] * vc[t];
                float nadd = wt[t] * (xr * xr + yr * yr);
                if (t & 1) sn1 += nadd; else sn0 += nadd;
            }

            // rotate register windows (pure renaming after full unroll)
#pragma unroll
            for (int t = 0; t < 4; ++t) {
                um2[t] = um1[t]; um1[t] = uc[t]; uc[t] = up1[t]; up1[t] = up2[t]; up2[t] = nu[t];
                vm2[t] = vm1[t]; vm1[t] = vc[t]; vc[t] = vp1[t]; vp1[t] = vp2[t]; vp2[t] = nv[t];
                pm1[t] = pc[t];  pc[t] = pp1[t]; pp1[t] = np[t];
            }
        }
    }

    float s_base = (sb0 + sb1) + (sb2 + sb3);
    float s_cont = sc0 + sc1;
    float s_ns   = sn0 + sn1;

    // ---------------- block reduction -> g_part ----------------
    {
        float vals[4] = {s_base, s_bc, s_cont, s_ns};
        __shared__ float rbuf[4][2];
#pragma unroll
        for (int k = 0; k < 4; ++k) {
            float v = vals[k];
#pragma unroll
            for (int off = 16; off; off >>= 1) v += __shfl_down_sync(0xffffffffu, v, off);
            if (lane == 0) rbuf[k][w] = v;
        }
        __syncthreads();
        if (tx == 0) {
#pragma unroll
            for (int k = 0; k < 4; ++k)
                g_part[blk][k] = rbuf[k][0] + rbuf[k][1];
        }
    }

    // ---------------- fused finalize: last block reduces all partials ----------------
    __shared__ int isLast;
    if (tx == 0) {
        __threadfence();
        unsigned t = atomicAdd(&g_ctr, 1u);
        isLast = (t == (unsigned)(NBLK - 1)) ? 1 : 0;
    }
    __syncthreads();

    if (isLast) {
        double a0 = 0.0, a1 = 0.0, a2 = 0.0, a3 = 0.0;
        const float4* gp = (const float4*)g_part;
        for (int idx = tx; idx < NBLK; idx += NTHR) {
            float4 v = __ldcg(&gp[idx]);
            a0 += (double)v.x; a1 += (double)v.y; a2 += (double)v.z; a3 += (double)v.w;
        }
#pragma unroll
        for (int off = 16; off; off >>= 1) {
            a0 += __shfl_down_sync(0xffffffffu, a0, off);
            a1 += __shfl_down_sync(0xffffffffu, a1, off);
            a2 += __shfl_down_sync(0xffffffffu, a2, off);
            a3 += __shfl_down_sync(0xffffffffu, a3, off);
        }
        __shared__ double sd[4][2];
        if (lane == 0) { sd[0][w] = a0; sd[1][w] = a1; sd[2][w] = a2; sd[3][w] = a3; }
        __syncthreads();
        if (tx == 0) {
            double t0 = sd[0][0] + sd[0][1];
            double t1 = sd[1][0] + sd[1][1];
            double t2 = sd[2][0] + sd[2][1];
            double t3 = sd[3][0] + sd[3][1];
            const double NI = 256.0 * 126.0 * 126.0;
            double loss_base = t0 / 300000.0;
            double loss_bc   = t1 / (256.0 * 988.0);
            double loss_cont = (t2 / NI) / 1e-5;
            double loss_ns   = (t3 / (NI * 2.0)) / 0.01;
            double A_LOSS = 1.0 - 0.3 - 0.3 - 0.3;
            out[0] = (float)(A_LOSS * loss_base + 0.3 * loss_cont + 0.3 * loss_ns + 0.3 * loss_bc);
            g_ctr = 0u;   // reset for graph replay
        }
    }
}

extern "C" void kernel_launch(void* const* d_in, const int* in_sizes, int n_in,
                              void* d_out, int out_size) {
    const int SMALL = 256 * 128 * 128;
    int idx_in = 0;
    for (int i = 0; i < n_in; ++i)
        if (in_sizes[i] == SMALL) { idx_in = i; break; }
    const float* inp = (const float*)d_in[idx_in];
    const float* big[2];
    int nb = 0;
    for (int i = 0; i < n_in && nb < 2; ++i)
        if (i != idx_in) big[nb++] = (const float*)d_in[i];
    const float* outp = big[0];
    const float* tgt  = big[1];

    physics_kernel<<<NBLK, NTHR>>>(inp, outp, tgt, (float*)d_out);
}

// round 13
// speedup vs baseline: 1.0713x; 1.0713x over previous
#include <cuda_runtime.h>

#define NBLK 1024   // 256 batches * 4 quarters; block = 2 warps * 16 rows each
#define NTHR 64     // 2 warps

__device__ float g_part[NBLK][4];
__device__ unsigned int g_ctr;

#define CP_ASYNC16(saddr, gptr) \
    asm volatile("cp.async.cg.shared.global [%0], [%1], 16;\n" :: "r"(saddr), "l"(gptr))
#define CP_COMMIT() asm volatile("cp.async.commit_group;\n" ::: "memory")
#define CP_WAIT2()  asm volatile("cp.async.wait_group 2;\n" ::: "memory")

__global__ __launch_bounds__(NTHR, 8) void physics_kernel(
    const float* __restrict__ inp,   // (256,1,128,128)
    const float* __restrict__ outp,  // (256,3,128,128)
    const float* __restrict__ tgt,   // (256,3,128,128)
    float* __restrict__ out)
{
    const int blk  = blockIdx.x;
    const int b    = blk >> 2;
    const int q    = blk & 3;
    const int tx   = threadIdx.x;
    const int lane = tx & 31;
    const int w    = tx >> 5;

    constexpr float INV_SX  = 127.0f / 1.2f;
    constexpr float INV_2SX = 127.0f / 2.4f;
    constexpr float INV_SY  = 127.0f / 0.8f;
    constexpr float INV_2SY = 127.0f / 1.6f;
    constexpr float C2X = INV_2SX * INV_2SX;
    constexpr float C2Y = INV_2SY * INV_2SY;

    const float* Ob = outp + b * 49152;
    const float* Tb = tgt  + b * 49152;
    const float* Ib = inp  + b * 16384;

    // split accumulators to break FMA dependency chains
    float sb0 = 0.f, sb1 = 0.f, sb2 = 0.f, sb3 = 0.f;
    float sc0 = 0.f, sc1 = 0.f;
    float sn0 = 0.f, sn1 = 0.f;
    float s_bc = 0.f;

    const int chunk = q * 2 + w;                 // 0..7
    const int y0  = chunk * 16;
    const int jlo = max(y0 - 1, 0);
    const int jhi = min(y0 + 15, 126);
    const int npde = jhi - jlo;                  // 15 or 16

    const float4* O4 = (const float4*)Ob;
    const float4* T4 = (const float4*)Tb;
    const float4* U4 = (const float4*)(Ob + 16384);
    const float4* V4 = (const float4*)(Ob + 32768);
    const float4* P4 = (const float4*)(Ob);
    const float4* A4 = (const float4*)(Ib);

    // warp-private cp.async ring: [warp][stage][array(o0,o1,o2,t0,t1,t2)][lane]
    __shared__ float4 sbuf[2][3][6][32];

    // issue cp.async for base row into stage s (one group per stage)
    auto issue_stage = [&](int s, int row) {
        int bi = row * 32 + lane;
        unsigned int sa = (unsigned int)__cvta_generic_to_shared(&sbuf[w][s][0][lane]);
        CP_ASYNC16(sa + 0u * 512u, (const void*)&O4[bi]);
        CP_ASYNC16(sa + 1u * 512u, (const void*)&O4[4096 + bi]);
        CP_ASYNC16(sa + 2u * 512u, (const void*)&O4[8192 + bi]);
        CP_ASYNC16(sa + 3u * 512u, (const void*)&T4[bi]);
        CP_ASYNC16(sa + 4u * 512u, (const void*)&T4[4096 + bi]);
        CP_ASYNC16(sa + 5u * 512u, (const void*)&T4[8192 + bi]);
        CP_COMMIT();
    };

    // prologue: 3 stages in flight
    issue_stage(0, y0 + 0);
    issue_stage(1, y0 + 1);
    issue_stage(2, y0 + 2);

#define ROWI(j) (((j) + 1) * 32 + lane)
#define LD4(dst, arrptr, j) { float4 _t = (arrptr)[ROWI(j)]; \
        dst[0]=_t.x; dst[1]=_t.y; dst[2]=_t.z; dst[3]=_t.w; }
#define LD4S(dst, arrptr, j) { float4 _t = __ldcs(&(arrptr)[ROWI(j)]); \
        dst[0]=_t.x; dst[1]=_t.y; dst[2]=_t.z; dst[3]=_t.w; }

    float um2[4], um1[4], uc[4], up1[4], up2[4];
    float vm2[4], vm1[4], vc[4], vp1[4], vp2[4];
    float pm1[4], pc[4], pp1[4];
#pragma unroll
    for (int t = 0; t < 4; ++t) {
        um2[t] = um1[t] = 0.f; vm2[t] = vm1[t] = 0.f; pm1[t] = 0.f;
    }

    if (jlo >= 2) { LD4(um2, U4, jlo - 2); LD4(vm2, V4, jlo - 2); }
    if (jlo >= 1) { LD4(um1, U4, jlo - 1); LD4(vm1, V4, jlo - 1); LD4(pm1, P4, jlo - 1); }
    LD4(uc,  U4, jlo);      LD4(vc,  V4, jlo);      LD4(pc,  P4, jlo);
    LD4(up1, U4, jlo + 1);  LD4(vp1, V4, jlo + 1);  LD4(pp1, P4, jlo + 1);
    LD4(up2, U4, jlo + 2);  LD4(vp2, V4, jlo + 2);

    float wt[4] = {1.f, 1.f, 1.f, 1.f};
    if (lane == 0)  wt[0] = 0.f;
    if (lane == 31) wt[3] = 0.f;

#pragma unroll
    for (int it = 0; it < 16; ++it) {
        const int j = jlo + it;
        const bool pde = (it < 15) || (it < npde);

        // ---- PDE prefetch loads (direct LDG) ----
        float nu[4] = {0,0,0,0}, nv[4] = {0,0,0,0}, np[4] = {0,0,0,0}, al[4] = {0,0,0,0};
        if (pde) {
            if (j + 3 <= 125) { LD4(nu, U4, j + 3); LD4(nv, V4, j + 3); }
            if (j + 2 <= 125) { LD4(np, P4, j + 2); }
            LD4S(al, A4, j);
        }

        // ---- base row from cp.async ring (issued 3 rows ago) ----
        CP_WAIT2();                             // oldest group (this row) complete
        const int st = it % 3;
        float4 o0 = sbuf[w][st][0][lane];
        float4 o1 = sbuf[w][st][1][lane];
        float4 o2 = sbuf[w][st][2][lane];
        float4 t0 = sbuf[w][st][3][lane];
        float4 t1 = sbuf[w][st][4][lane];
        float4 t2 = sbuf[w][st][5][lane];
        // refill stage with row it+3 (or commit empty group to keep count)
        if (it + 3 < 16) issue_stage((it + 3) % 3, y0 + it + 3);
        else             CP_COMMIT();

        const int yb = y0 + it;

        // ---- base + boundary compute ----
        {
            float d;
            d = o0.x - t0.x; sb0 += d * d;  d = o0.y - t0.y; sb1 += d * d;
            d = o0.z - t0.z; sb2 += d * d;  d = o0.w - t0.w; sb3 += d * d;
            d = o1.x - t1.x; sb0 += d * d;  d = o1.y - t1.y; sb1 += d * d;
            d = o1.z - t1.z; sb2 += d * d;  d = o1.w - t1.w; sb3 += d * d;
            d = o2.x - t2.x; sb0 += d * d;  d = o2.y - t2.y; sb1 += d * d;
            d = o2.z - t2.z; sb2 += d * d;  d = o2.w - t2.w; sb3 += d * d;

            bool midrow = (yb >= 55) && (yb < 73);
            if (yb == 0 || yb == 127)
                s_bc += o1.x * o1.x + o1.y * o1.y + o1.z * o1.z + o1.w * o1.w
                      + o2.x * o2.x + o2.y * o2.y + o2.z * o2.z + o2.w * o2.w;
            if (lane == 0) {
                if (midrow) { float e = o1.x - 0.01f; s_bc += e * e; }
                else        s_bc += o1.x * o1.x + o2.x * o2.x;
            }
            if (lane == 31) {
                if (midrow) s_bc += o0.w * o0.w;
                else        s_bc += o1.w * o1.w + o2.w * o2.w;
            }
        }

        // ---- PDE compute ----
        if (pde) {
            float upz = __shfl_up_sync(0xffffffffu, uc[2], 1);
            float upw = __shfl_up_sync(0xffffffffu, uc[3], 1);
            float unx = __shfl_down_sync(0xffffffffu, uc[0], 1);
            float uny = __shfl_down_sync(0xffffffffu, uc[1], 1);
            float vpz = __shfl_up_sync(0xffffffffu, vc[2], 1);
            float vpw = __shfl_up_sync(0xffffffffu, vc[3], 1);
            float vnx = __shfl_down_sync(0xffffffffu, vc[0], 1);
            float vny = __shfl_down_sync(0xffffffffu, vc[1], 1);
            float ppw = __shfl_up_sync(0xffffffffu, pc[3], 1);
            float pnx = __shfl_down_sync(0xffffffffu, pc[0], 1);

            float uw[8] = {upz, upw, uc[0], uc[1], uc[2], uc[3], unx, uny};
            float vw[8] = {vpz, vpw, vc[0], vc[1], vc[2], vc[3], vnx, vny};
            float pw[8] = {0.f, ppw, pc[0], pc[1], pc[2], pc[3], pnx, 0.f};

            float du_dx[4], du_dxx[4], dv_dx[4], dv_dxx[4], dp_dx[4];
#pragma unroll
            for (int t = 0; t < 4; ++t) {
                du_dx[t]  = (uw[t + 3] - uw[t + 1]) * INV_2SX;
                du_dxx[t] = (uw[t + 4] - 2.f * uw[t + 2] + uw[t]) * C2X;
                dv_dx[t]  = (vw[t + 3] - vw[t + 1]) * INV_2SX;
                dv_dxx[t] = (vw[t + 4] - 2.f * vw[t + 2] + vw[t]) * C2X;
                dp_dx[t]  = (pw[t + 3] - pw[t + 1]) * INV_2SX;
            }
            if (lane == 0) {
                du_dx[1]  = (uw[4] - uw[3]) * INV_SX;
                du_dxx[1] = ((uw[5] - uw[3]) * INV_2SX - (uw[4] - uw[3]) * INV_SX) * INV_SX;
                du_dxx[2] = ((uw[6] - uw[4]) * INV_2SX - (uw[4] - uw[3]) * INV_SX) * INV_2SX;
                dv_dx[1]  = (vw[4] - vw[3]) * INV_SX;
                dv_dxx[1] = ((vw[5] - vw[3]) * INV_2SX - (vw[4] - vw[3]) * INV_SX) * INV_SX;
                dv_dxx[2] = ((vw[6] - vw[4]) * INV_2SX - (vw[4] - vw[3]) * INV_SX) * INV_2SX;
                dp_dx[1]  = (pw[4] - pw[3]) * INV_SX;
            }
            if (lane == 31) {
                du_dxx[1] = ((uw[4] - uw[3]) * INV_SX - (uw[3] - uw[1]) * INV_2SX) * INV_2SX;
                du_dx[2]  = (uw[4] - uw[3]) * INV_SX;
                du_dxx[2] = ((uw[4] - uw[3]) * INV_SX - (uw[4] - uw[2]) * INV_2SX) * INV_SX;
                dv_dxx[1] = ((vw[4] - vw[3]) * INV_SX - (vw[3] - vw[1]) * INV_2SX) * INV_2SX;
                dv_dx[2]  = (vw[4] - vw[3]) * INV_SX;
                dv_dxx[2] = ((vw[4] - vw[3]) * INV_SX - (vw[4] - vw[2]) * INV_2SX) * INV_SX;
                dp_dx[2]  = (pw[4] - pw[3]) * INV_SX;
            }

            float du_dy[4], du_dyy[4], dv_dy[4], dv_dyy[4], dp_dy[4];
#pragma unroll
            for (int t = 0; t < 4; ++t) {
                du_dy[t]  = (up1[t] - um1[t]) * INV_2SY;
                du_dyy[t] = (up2[t] - 2.f * uc[t] + um2[t]) * C2Y;
                dv_dy[t]  = (vp1[t] - vm1[t]) * INV_2SY;
                dv_dyy[t] = (vp2[t] - 2.f * vc[t] + vm2[t]) * C2Y;
                dp_dy[t]  = (pp1[t] - pm1[t]) * INV_2SY;
            }
            if (j < 2 || j > 123) {
                if (j == 0) {
#pragma unroll
                    for (int t = 0; t < 4; ++t) {
                        du_dy[t]  = (up1[t] - uc[t]) * INV_SY;
                        du_dyy[t] = ((up2[t] - uc[t]) * INV_2SY - (up1[t] - uc[t]) * INV_SY) * INV_SY;
                        dv_dy[t]  = (vp1[t] - vc[t]) * INV_SY;
                        dv_dyy[t] = ((vp2[t] - vc[t]) * INV_2SY - (vp1[t] - vc[t]) * INV_SY) * INV_SY;
                        dp_dy[t]  = (pp1[t] - pc[t]) * INV_SY;
                    }
                } else if (j == 1) {
#pragma unroll
                    for (int t = 0; t < 4; ++t) {
                        du_dyy[t] = ((up2[t] - uc[t]) * INV_2SY - (uc[t] - um1[t]) * INV_SY) * INV_2SY;
                        dv_dyy[t] = ((vp2[t] - vc[t]) * INV_2SY - (vc[t] - vm1[t]) * INV_SY) * INV_2SY;
                    }
                } else if (j == 124) {
#pragma unroll
                    for (int t = 0; t < 4; ++t) {
                        du_dyy[t] = ((up1[t] - uc[t]) * INV_SY - (uc[t] - um2[t]) * INV_2SY) * INV_2SY;
                        dv_dyy[t] = ((vp1[t] - vc[t]) * INV_SY - (vc[t] - vm2[t]) * INV_2SY) * INV_2SY;
                    }
                } else { // j == 125
#pragma unroll
                    for (int t = 0; t < 4; ++t) {
                        du_dy[t]  = (uc[t] - um1[t]) * INV_SY;
                        du_dyy[t] = ((uc[t] - um1[t]) * INV_SY - (uc[t] - um2[t]) * INV_2SY) * INV_SY;
                        dv_dy[t]  = (vc[t] - vm1[t]) * INV_SY;
                        dv_dyy[t] = ((vc[t] - vm1[t]) * INV_SY - (vc[t] - vm2[t]) * INV_2SY) * INV_SY;
                        dp_dy[t]  = (pc[t] - pm1[t]) * INV_SY;
                    }
                }
            }

#pragma unroll
            for (int t = 0; t < 4; ++t) {
                float div = du_dx[t] + dv_dy[t];
                float cadd = wt[t] * div * div;
                if (t & 1) sc1 += cadd; else sc0 += cadd;
                float xr = uc[t] * du_dx[t] + vc[t] * du_dy[t] + dp_dx[t]
                         - (du_dxx[t] + du_dyy[t]) + al[t] * uc[t];
                float yr = uc[t] * dv_dx[t] + vc[t] * dv_dy[t] + dp_dy[t]
                         - (dv_dxx[t] + dv_dyy[t]) + al[t] * vc[t];
                float nadd = wt[t] * (xr * xr + yr * yr);
                if (t & 1) sn1 += nadd; else sn0 += nadd;
            }

            // rotate register windows (pure renaming after full unroll)
#pragma unroll
            for (int t = 0; t < 4; ++t) {
                um2[t] = um1[t]; um1[t] = uc[t]; uc[t] = up1[t]; up1[t] = up2[t]; up2[t] = nu[t];
                vm2[t] = vm1[t]; vm1[t] = vc[t]; vc[t] = vp1[t]; vp1[t] = vp2[t]; vp2[t] = nv[t];
                pm1[t] = pc[t];  pc[t] = pp1[t]; pp1[t] = np[t];
            }
        }
    }

    float s_base = (sb0 + sb1) + (sb2 + sb3);
    float s_cont = sc0 + sc1;
    float s_ns   = sn0 + sn1;

    // ---------------- block reduction -> g_part ----------------
    {
        float vals[4] = {s_base, s_bc, s_cont, s_ns};
        __shared__ float rbuf[4][2];
#pragma unroll
        for (int k = 0; k < 4; ++k) {
            float v = vals[k];
#pragma unroll
            for (int off = 16; off; off >>= 1) v += __shfl_down_sync(0xffffffffu, v, off);
            if (lane == 0) rbuf[k][w] = v;
        }
        __syncthreads();
        if (tx == 0) {
#pragma unroll
            for (int k = 0; k < 4; ++k)
                g_part[blk][k] = rbuf[k][0] + rbuf[k][1];
        }
    }

    // ---------------- fused finalize: last block reduces all partials ----------------
    __shared__ int isLast;
    if (tx == 0) {
        __threadfence();
        unsigned t = atomicAdd(&g_ctr, 1u);
        isLast = (t == (unsigned)(NBLK - 1)) ? 1 : 0;
    }
    __syncthreads();

    if (isLast) {
        double a0 = 0.0, a1 = 0.0, a2 = 0.0, a3 = 0.0;
        const float4* gp = (const float4*)g_part;
        for (int idx = tx; idx < NBLK; idx += NTHR) {
            float4 v = __ldcg(&gp[idx]);
            a0 += (double)v.x; a1 += (double)v.y; a2 += (double)v.z; a3 += (double)v.w;
        }
#pragma unroll
        for (int off = 16; off; off >>= 1) {
            a0 += __shfl_down_sync(0xffffffffu, a0, off);
            a1 += __shfl_down_sync(0xffffffffu, a1, off);
            a2 += __shfl_down_sync(0xffffffffu, a2, off);
            a3 += __shfl_down_sync(0xffffffffu, a3, off);
        }
        __shared__ double sd[4][2];
        if (lane == 0) { sd[0][w] = a0; sd[1][w] = a1; sd[2][w] = a2; sd[3][w] = a3; }
        __syncthreads();
        if (tx == 0) {
            double t0 = sd[0][0] + sd[0][1];
            double t1 = sd[1][0] + sd[1][1];
            double t2 = sd[2][0] + sd[2][1];
            double t3 = sd[3][0] + sd[3][1];
            const double NI = 256.0 * 126.0 * 126.0;
            double loss_base = t0 / 300000.0;
            double loss_bc   = t1 / (256.0 * 988.0);
            double loss_cont = (t2 / NI) / 1e-5;
            double loss_ns   = (t3 / (NI * 2.0)) / 0.01;
            double A_LOSS = 1.0 - 0.3 - 0.3 - 0.3;
            out[0] = (float)(A_LOSS * loss_base + 0.3 * loss_cont + 0.3 * loss_ns + 0.3 * loss_bc);
            g_ctr = 0u;   // reset for graph replay
        }
    }
}

extern "C" void kernel_launch(void* const* d_in, const int* in_sizes, int n_in,
                              void* d_out, int out_size) {
    const int SMALL = 256 * 128 * 128;
    int idx_in = 0;
    for (int i = 0; i < n_in; ++i)
        if (in_sizes[i] == SMALL) { idx_in = i; break; }
    const float* inp = (const float*)d_in[idx_in];
    const float* big[2];
    int nb = 0;
    for (int i = 0; i < n_in && nb < 2; ++i)
        if (i != idx_in) big[nb++] = (const float*)d_in[i];
    const float* outp = big[0];
    const float* tgt  = big[1];

    physics_kernel<<<NBLK, NTHR>>>(inp, outp, tgt, (float*)d_out);
}